// round 2
// baseline (speedup 1.0000x reference)
#include <cuda_runtime.h>

#define SEQ   2048
#define DIM   4096
#define NH    32
#define NKV   8
#define HD    128
#define KVDIM 1024   // NKV*HD

// ---------------- scratch (static device globals; no allocations) ----------
__device__ float g_q[SEQ * DIM];     // 32 MB  roped Q   [s][h*128+d]
__device__ float g_k[SEQ * KVDIM];   //  8 MB  roped K   [s][kh*128+d]
__device__ float g_v[SEQ * KVDIM];   //  8 MB  V
__device__ float g_a[SEQ * DIM];     // 32 MB  attention out

// ---------------- SGEMM: C[M,N] = A[M,K] @ B[K,N], all row-major -----------
// 128x128 block tile, BK=8, 256 threads, 8x8 per thread.
__global__ __launch_bounds__(256, 2)
void sgemm128(const float* __restrict__ A, const float* __restrict__ B,
              float* __restrict__ C, int M, int N, int K)
{
    __shared__ float As[8][128];   // [k][m]
    __shared__ float Bs[8][128];   // [k][n]

    const int tid = threadIdx.x;
    const int tr  = tid >> 4;          // 0..15
    const int tc  = tid & 15;          // 0..15
    const int rowBase = blockIdx.y * 128;
    const int colBase = blockIdx.x * 128;

    const int aRow = tid >> 1;         // 0..127
    const int aCol = (tid & 1) * 4;    // 0 or 4
    const int bRow = tid >> 5;         // 0..7
    const int bCol = (tid & 31) * 4;   // 0..124

    const float* Aptr = A + (size_t)(rowBase + aRow) * K + aCol;
    const float* Bptr = B + (size_t)bRow * N + colBase + bCol;

    float acc[8][8];
    #pragma unroll
    for (int i = 0; i < 8; i++)
        #pragma unroll
        for (int j = 0; j < 8; j++) acc[i][j] = 0.f;

    for (int k0 = 0; k0 < K; k0 += 8) {
        float4 av = *(const float4*)(Aptr + k0);
        As[aCol + 0][aRow] = av.x;
        As[aCol + 1][aRow] = av.y;
        As[aCol + 2][aRow] = av.z;
        As[aCol + 3][aRow] = av.w;
        *(float4*)&Bs[bRow][bCol] = *(const float4*)(Bptr + (size_t)k0 * N);
        __syncthreads();

        #pragma unroll
        for (int kk = 0; kk < 8; kk++) {
            float4 a0 = *(const float4*)&As[kk][tr * 8];
            float4 a1 = *(const float4*)&As[kk][tr * 8 + 4];
            float4 b0 = *(const float4*)&Bs[kk][tc * 8];
            float4 b1 = *(const float4*)&Bs[kk][tc * 8 + 4];
            float ra[8] = {a0.x, a0.y, a0.z, a0.w, a1.x, a1.y, a1.z, a1.w};
            float rb[8] = {b0.x, b0.y, b0.z, b0.w, b1.x, b1.y, b1.z, b1.w};
            #pragma unroll
            for (int i = 0; i < 8; i++)
                #pragma unroll
                for (int j = 0; j < 8; j++)
                    acc[i][j] = fmaf(ra[i], rb[j], acc[i][j]);
        }
        __syncthreads();
    }

    #pragma unroll
    for (int i = 0; i < 8; i++) {
        float* Crow = C + (size_t)(rowBase + tr * 8 + i) * N + colBase + tc * 8;
        *(float4*)Crow       = make_float4(acc[i][0], acc[i][1], acc[i][2], acc[i][3]);
        *(float4*)(Crow + 4) = make_float4(acc[i][4], acc[i][5], acc[i][6], acc[i][7]);
    }
}

// ---------------- RoPE (in-place on g_q and g_k) ---------------------------
// freqs layout: [s][64][{cos,sin}] -> f[s*128 + 2*i + {0,1}]
__global__ void rope_kernel(float* __restrict__ q, float* __restrict__ k,
                            const float* __restrict__ f)
{
    int idx = blockIdx.x * blockDim.x + threadIdx.x;
    const int total = SEQ * (NH + NKV) * (HD / 2);
    if (idx >= total) return;
    int i = idx & 63;                 // pair index 0..63
    int h = (idx >> 6) % (NH + NKV);  // 0..39
    int s = idx / ((NH + NKV) * 64);

    float c = f[s * 128 + 2 * i];
    float d = f[s * 128 + 2 * i + 1];
    float* base = (h < NH) ? (q + (size_t)s * DIM   + h * HD        + 2 * i)
                           : (k + (size_t)s * KVDIM + (h - NH) * HD + 2 * i);
    float a = base[0], b = base[1];
    base[0] = a * c - b * d;
    base[1] = a * d + b * c;
}

// ---------------- causal flash attention (fp32, GQA) -----------------------
#define BQ   64
#define BKV  64
#define QPAD 132    // floats per smem row (128 + 4): keeps float4 alignment
#define PPAD 65

__device__ __forceinline__ float redmax16(float v) {
    v = fmaxf(v, __shfl_xor_sync(0xffffffffu, v, 1));
    v = fmaxf(v, __shfl_xor_sync(0xffffffffu, v, 2));
    v = fmaxf(v, __shfl_xor_sync(0xffffffffu, v, 4));
    v = fmaxf(v, __shfl_xor_sync(0xffffffffu, v, 8));
    return v;
}
__device__ __forceinline__ float redsum16(float v) {
    v += __shfl_xor_sync(0xffffffffu, v, 1);
    v += __shfl_xor_sync(0xffffffffu, v, 2);
    v += __shfl_xor_sync(0xffffffffu, v, 4);
    v += __shfl_xor_sync(0xffffffffu, v, 8);
    return v;
}

__global__ __launch_bounds__(256, 2)
void flash_kernel(const float* __restrict__ q, const float* __restrict__ k,
                  const float* __restrict__ v, float* __restrict__ o)
{
    extern __shared__ float sh[];
    float* Qs  = sh;                   // BQ  * QPAD
    float* KVs = Qs + BQ * QPAD;       // BKV * QPAD  (K, then reused for V)
    float* Ps  = KVs + BKV * QPAD;     // BQ  * PPAD

    const int tid = threadIdx.x;
    const int ty  = tid >> 4;          // 0..15
    const int tx  = tid & 15;          // 0..15
    const int h   = blockIdx.y;        // 0..31
    const int qt  = blockIdx.x;        // 0..31
    const int q0  = qt * BQ;
    const int kh  = h >> 2;            // GQA: 4 q-heads per kv-head
    const float scale = 0.08838834764831845f;   // 1/sqrt(128)

    // load Q tile (pre-scaled)
    for (int idx = tid; idx < BQ * (HD / 4); idx += 256) {
        int r = idx >> 5, c4 = idx & 31;
        float4 t = *(const float4*)(q + (size_t)(q0 + r) * DIM + h * HD + c4 * 4);
        t.x *= scale; t.y *= scale; t.z *= scale; t.w *= scale;
        *(float4*)(Qs + r * QPAD + c4 * 4) = t;
    }

    float m_i[4], l_i[4], O[4][8];
    #pragma unroll
    for (int i = 0; i < 4; i++) {
        m_i[i] = -1e30f; l_i[i] = 0.f;
        #pragma unroll
        for (int c = 0; c < 8; c++) O[i][c] = 0.f;
    }
    __syncthreads();

    for (int kt = 0; kt <= qt; kt++) {
        const int k0 = kt * BKV;

        // ---- load K tile
        for (int idx = tid; idx < BKV * (HD / 4); idx += 256) {
            int r = idx >> 5, c4 = idx & 31;
            *(float4*)(KVs + r * QPAD + c4 * 4) =
                *(const float4*)(k + (size_t)(k0 + r) * KVDIM + kh * HD + c4 * 4);
        }
        __syncthreads();

        // ---- scores: S[r][j] = Q[r,:] . K[j,:]   (rows r=ty+16i, cols j=tx+16j)
        float s[4][4];
        #pragma unroll
        for (int i = 0; i < 4; i++)
            #pragma unroll
            for (int j = 0; j < 4; j++) s[i][j] = 0.f;

        const float4* Q4 = (const float4*)Qs;
        const float4* K4 = (const float4*)KVs;
        #pragma unroll 4
        for (int d4 = 0; d4 < HD / 4; d4++) {
            float4 qa[4], kb[4];
            #pragma unroll
            for (int i = 0; i < 4; i++) qa[i] = Q4[(ty + 16 * i) * (QPAD / 4) + d4];
            #pragma unroll
            for (int j = 0; j < 4; j++) kb[j] = K4[(tx + 16 * j) * (QPAD / 4) + d4];
            #pragma unroll
            for (int i = 0; i < 4; i++)
                #pragma unroll
                for (int j = 0; j < 4; j++) {
                    s[i][j] = fmaf(qa[i].x, kb[j].x, s[i][j]);
                    s[i][j] = fmaf(qa[i].y, kb[j].y, s[i][j]);
                    s[i][j] = fmaf(qa[i].z, kb[j].z, s[i][j]);
                    s[i][j] = fmaf(qa[i].w, kb[j].w, s[i][j]);
                }
        }

        // ---- causal mask on the diagonal tile
        if (kt == qt) {
            #pragma unroll
            for (int i = 0; i < 4; i++)
                #pragma unroll
                for (int j = 0; j < 4; j++)
                    if (tx + 16 * j > ty + 16 * i) s[i][j] = -1e30f;
        }

        // ---- online softmax update; write P to smem
        #pragma unroll
        for (int i = 0; i < 4; i++) {
            float rm = fmaxf(fmaxf(s[i][0], s[i][1]), fmaxf(s[i][2], s[i][3]));
            rm = redmax16(rm);
            float mn = fmaxf(m_i[i], rm);
            float alpha = __expf(m_i[i] - mn);
            float rs = 0.f;
            #pragma unroll
            for (int j = 0; j < 4; j++) {
                float p = __expf(s[i][j] - mn);
                rs += p;
                Ps[(ty + 16 * i) * PPAD + tx + 16 * j] = p;
            }
            rs = redsum16(rs);
            l_i[i] = l_i[i] * alpha + rs;
            m_i[i] = mn;
            #pragma unroll
            for (int c = 0; c < 8; c++) O[i][c] *= alpha;
        }
        __syncthreads();   // P written; K reads done

        // ---- load V tile (reuse KVs)
        for (int idx = tid; idx < BKV * (HD / 4); idx += 256) {
            int r = idx >> 5, c4 = idx & 31;
            *(float4*)(KVs + r * QPAD + c4 * 4) =
                *(const float4*)(v + (size_t)(k0 + r) * KVDIM + kh * HD + c4 * 4);
        }
        __syncthreads();

        // ---- O += P @ V    (O cols = tx*8 .. tx*8+7)
        const float4* V4 = (const float4*)KVs;
        #pragma unroll 4
        for (int j = 0; j < BKV; j++) {
            float pv[4];
            #pragma unroll
            for (int i = 0; i < 4; i++) pv[i] = Ps[(ty + 16 * i) * PPAD + j];
            float4 v0 = V4[j * (QPAD / 4) + tx * 2];
            float4 v1 = V4[j * (QPAD / 4) + tx * 2 + 1];
            #pragma unroll
            for (int i = 0; i < 4; i++) {
                O[i][0] = fmaf(pv[i], v0.x, O[i][0]);
                O[i][1] = fmaf(pv[i], v0.y, O[i][1]);
                O[i][2] = fmaf(pv[i], v0.z, O[i][2]);
                O[i][3] = fmaf(pv[i], v0.w, O[i][3]);
                O[i][4] = fmaf(pv[i], v1.x, O[i][4]);
                O[i][5] = fmaf(pv[i], v1.y, O[i][5]);
                O[i][6] = fmaf(pv[i], v1.z, O[i][6]);
                O[i][7] = fmaf(pv[i], v1.w, O[i][7]);
            }
        }
        __syncthreads();   // Ps/KVs consumed; safe to overwrite next iter
    }

    // ---- epilogue: normalize and store
    #pragma unroll
    for (int i = 0; i < 4; i++) {
        float inv = 1.f / l_i[i];
        int r = q0 + ty + 16 * i;
        float* dst = o + (size_t)r * DIM + h * HD + tx * 8;
        *(float4*)dst       = make_float4(O[i][0] * inv, O[i][1] * inv,
                                          O[i][2] * inv, O[i][3] * inv);
        *(float4*)(dst + 4) = make_float4(O[i][4] * inv, O[i][5] * inv,
                                          O[i][6] * inv, O[i][7] * inv);
    }
}

// ---------------- launch ----------------------------------------------------
extern "C" void kernel_launch(void* const* d_in, const int* in_sizes, int n_in,
                              void* d_out, int out_size)
{
    const float* x  = (const float*)d_in[0];
    // d_in[1] = cache_kv: unused (start_pos==0 => cache is pass-through)
    const float* fr = (const float*)d_in[2];
    const float* wq = (const float*)d_in[3];
    const float* wk = (const float*)d_in[4];
    const float* wv = (const float*)d_in[5];
    const float* wo = (const float*)d_in[6];
    float* out = (float*)d_out;

    float *pq, *pk, *pv, *pa;
    cudaGetSymbolAddress((void**)&pq, g_q);
    cudaGetSymbolAddress((void**)&pk, g_k);
    cudaGetSymbolAddress((void**)&pv, g_v);
    cudaGetSymbolAddress((void**)&pa, g_a);

    const int flash_smem = (BQ * QPAD + BKV * QPAD + BQ * PPAD) * (int)sizeof(float);
    cudaFuncSetAttribute(flash_kernel, cudaFuncAttributeMaxDynamicSharedMemorySize,
                         flash_smem);

    dim3 blk(256);
    // QKV projections
    sgemm128<<<dim3(DIM / 128,   SEQ / 128), blk>>>(x, wq, pq, SEQ, DIM,   DIM);
    sgemm128<<<dim3(KVDIM / 128, SEQ / 128), blk>>>(x, wk, pk, SEQ, KVDIM, DIM);
    sgemm128<<<dim3(KVDIM / 128, SEQ / 128), blk>>>(x, wv, pv, SEQ, KVDIM, DIM);
    // RoPE on q and k
    const int rope_total = SEQ * (NH + NKV) * (HD / 2);
    rope_kernel<<<(rope_total + 255) / 256, 256>>>(pq, pk, fr);
    // causal GQA flash attention
    flash_kernel<<<dim3(SEQ / BQ, NH), blk, flash_smem>>>(pq, pk, pv, pa);
    // output projection
    sgemm128<<<dim3(DIM / 128, SEQ / 128), blk>>>(pa, wo, out, SEQ, DIM, DIM);
}

// round 4
// speedup vs baseline: 1.6318x; 1.6318x over previous
#include <cuda_runtime.h>

#define SEQ   2048
#define DIM   4096
#define NH    32
#define NKV   8
#define HD    128
#define KVDIM 1024   // NKV*HD

// ---------------- scratch (static device globals; no allocations) ----------
__device__ float g_q[SEQ * DIM];     // roped Q   [s][h*128+d]
__device__ float g_k[SEQ * KVDIM];   // roped K   [s][kh*128+d]
__device__ float g_v[SEQ * KVDIM];   // V
__device__ float g_a[SEQ * DIM];     // attention out

// ---------------- tf32 helpers ---------------------------------------------
__device__ __forceinline__ unsigned f2tf(float f) {
    unsigned r;
    asm("cvt.rna.tf32.f32 %0, %1;" : "=r"(r) : "f"(f));
    return r;
}

// D += A(16x8,row) * B(8x8,col)  tf32, fp32 accum
__device__ __forceinline__ void mma8(float* c,
                                     unsigned a0, unsigned a1, unsigned a2, unsigned a3,
                                     unsigned b0, unsigned b1) {
    asm volatile(
        "mma.sync.aligned.m16n8k8.row.col.f32.tf32.tf32.f32 "
        "{%0,%1,%2,%3}, {%4,%5,%6,%7}, {%8,%9}, {%0,%1,%2,%3};"
        : "+f"(c[0]), "+f"(c[1]), "+f"(c[2]), "+f"(c[3])
        : "r"(a0), "r"(a1), "r"(a2), "r"(a3), "r"(b0), "r"(b1));
}

// ---------------- tf32 GEMM: C[M,N] = A[M,K] @ B[K,N], row-major ------------
// 128x128x32 block tile, 256 threads (8 warps, 2x4 warp grid, 64x32 warp tile)
#define GBK  32
#define ASTR 136   // As [k][m], (136%32)=8 : banks 8*tg + g -> conflict-free
#define BSTR 136   // Bs [k][n]

__global__ __launch_bounds__(256, 1)
void gemm_tf32(const float* __restrict__ A, const float* __restrict__ B,
               float* __restrict__ C, int M, int N, int K)
{
    __shared__ unsigned As[GBK * ASTR];
    __shared__ unsigned Bs[GBK * BSTR];

    const int tid  = threadIdx.x;
    const int lane = tid & 31;
    const int wid  = tid >> 5;
    const int g    = lane >> 2;      // 0..7
    const int tg   = lane & 3;       // 0..3
    const int wm   = (wid & 1) * 64; // warp M base
    const int wn   = (wid >> 1) * 32;// warp N base
    const int rowBase = blockIdx.y * 128;
    const int colBase = blockIdx.x * 128;

    // A load map: m = tid&127 (lane-consecutive -> conflict-free STS),
    // k-group = tid>>7 (+2 per j). B load map: coalesced rows of float4.
    const int am  = tid & 127;
    const int akg = tid >> 7;      // 0/1
    const int bc4 = tid & 31;
    const int bk  = tid >> 5;      // 0..7

    const float* Abase = A + (size_t)(rowBase + am) * K;
    const float* Bbase = B + colBase + bc4 * 4;

    float4 ra[4], rb[4];
    float  acc[4][4][4];
    #pragma unroll
    for (int mi = 0; mi < 4; mi++)
        #pragma unroll
        for (int ni = 0; ni < 4; ni++)
            #pragma unroll
            for (int c = 0; c < 4; c++) acc[mi][ni][c] = 0.f;

    // prologue: load + store tile 0
    #pragma unroll
    for (int j = 0; j < 4; j++) {
        ra[j] = *(const float4*)(Abase + (akg + 2 * j) * 4);
        rb[j] = *(const float4*)(Bbase + (size_t)(bk + 8 * j) * N);
    }
    #pragma unroll
    for (int j = 0; j < 4; j++) {
        int kc = (akg + 2 * j) * 4;
        As[(kc + 0) * ASTR + am] = f2tf(ra[j].x);
        As[(kc + 1) * ASTR + am] = f2tf(ra[j].y);
        As[(kc + 2) * ASTR + am] = f2tf(ra[j].z);
        As[(kc + 3) * ASTR + am] = f2tf(ra[j].w);
        uint4 bv;
        bv.x = f2tf(rb[j].x); bv.y = f2tf(rb[j].y);
        bv.z = f2tf(rb[j].z); bv.w = f2tf(rb[j].w);
        *(uint4*)&Bs[(bk + 8 * j) * BSTR + bc4 * 4] = bv;
    }
    __syncthreads();

    const int T = K / GBK;
    for (int t = 0; t < T; ++t) {
        if (t + 1 < T) {  // prefetch next tile into registers
            const float* Ab = Abase + (t + 1) * GBK;
            const float* Bb = Bbase + (size_t)(t + 1) * GBK * N;
            #pragma unroll
            for (int j = 0; j < 4; j++) {
                ra[j] = *(const float4*)(Ab + (akg + 2 * j) * 4);
                rb[j] = *(const float4*)(Bb + (size_t)(bk + 8 * j) * N);
            }
        }
        #pragma unroll
        for (int ks = 0; ks < 4; ++ks) {
            unsigned a[4][4], b[4][2];
            const int k0 = ks * 8;
            #pragma unroll
            for (int mi = 0; mi < 4; mi++) {
                int mb = wm + mi * 16;
                a[mi][0] = As[(k0 + tg) * ASTR + mb + g];
                a[mi][1] = As[(k0 + tg) * ASTR + mb + g + 8];
                a[mi][2] = As[(k0 + tg + 4) * ASTR + mb + g];
                a[mi][3] = As[(k0 + tg + 4) * ASTR + mb + g + 8];
            }
            #pragma unroll
            for (int ni = 0; ni < 4; ni++) {
                b[ni][0] = Bs[(k0 + tg) * BSTR + wn + ni * 8 + g];
                b[ni][1] = Bs[(k0 + tg + 4) * BSTR + wn + ni * 8 + g];
            }
            #pragma unroll
            for (int mi = 0; mi < 4; mi++)
                #pragma unroll
                for (int ni = 0; ni < 4; ni++)
                    mma8(acc[mi][ni], a[mi][0], a[mi][1], a[mi][2], a[mi][3],
                         b[ni][0], b[ni][1]);
        }
        __syncthreads();
        if (t + 1 < T) {
            #pragma unroll
            for (int j = 0; j < 4; j++) {
                int kc = (akg + 2 * j) * 4;
                As[(kc + 0) * ASTR + am] = f2tf(ra[j].x);
                As[(kc + 1) * ASTR + am] = f2tf(ra[j].y);
                As[(kc + 2) * ASTR + am] = f2tf(ra[j].z);
                As[(kc + 3) * ASTR + am] = f2tf(ra[j].w);
                uint4 bv;
                bv.x = f2tf(rb[j].x); bv.y = f2tf(rb[j].y);
                bv.z = f2tf(rb[j].z); bv.w = f2tf(rb[j].w);
                *(uint4*)&Bs[(bk + 8 * j) * BSTR + bc4 * 4] = bv;
            }
            __syncthreads();
        }
    }

    // epilogue
    #pragma unroll
    for (int mi = 0; mi < 4; mi++) {
        #pragma unroll
        for (int ni = 0; ni < 4; ni++) {
            int r0 = rowBase + wm + mi * 16 + g;
            int cc = colBase + wn + ni * 8 + tg * 2;
            float2 t0; t0.x = acc[mi][ni][0]; t0.y = acc[mi][ni][1];
            float2 t1; t1.x = acc[mi][ni][2]; t1.y = acc[mi][ni][3];
            *(float2*)&C[(size_t)r0 * N + cc]       = t0;
            *(float2*)&C[(size_t)(r0 + 8) * N + cc] = t1;
        }
    }
}

// ---------------- RoPE (in-place on g_q and g_k) ---------------------------
__global__ void rope_kernel(float* __restrict__ q, float* __restrict__ k,
                            const float* __restrict__ f)
{
    int idx = blockIdx.x * blockDim.x + threadIdx.x;
    const int total = SEQ * (NH + NKV) * (HD / 2);
    if (idx >= total) return;
    int i = idx & 63;
    int h = (idx >> 6) % (NH + NKV);
    int s = idx / ((NH + NKV) * 64);

    float c = f[s * 128 + 2 * i];
    float d = f[s * 128 + 2 * i + 1];
    float* base = (h < NH) ? (q + (size_t)s * DIM   + h * HD        + 2 * i)
                           : (k + (size_t)s * KVDIM + (h - NH) * HD + 2 * i);
    float a = base[0], b = base[1];
    base[0] = a * c - b * d;
    base[1] = a * d + b * c;
}

// ---------------- causal flash attention (tf32 mma, GQA) -------------------
// 128 threads = 4 warps; warp w owns q rows [w*16, w*16+16); Q held as
// register A-fragments. Smem: K [j][d] str 132, V [kv][d] str 136, P str 68.
#define KSTR 132
#define VSTR 136
#define PSTR 68
#define FLASH_SMEM ((64 * KSTR + 64 * VSTR + 64 * PSTR) * 4)

__global__ __launch_bounds__(128, 2)
void flash_tf32(const float* __restrict__ q, const float* __restrict__ k,
                const float* __restrict__ v, float* __restrict__ o)
{
    extern __shared__ unsigned sh[];
    unsigned* Ks = sh;
    unsigned* Vs = Ks + 64 * KSTR;
    unsigned* Ps = Vs + 64 * VSTR;

    const int tid = threadIdx.x, lane = tid & 31, w = tid >> 5;
    const int g = lane >> 2, tg = lane & 3;
    const int h = blockIdx.y, qt = blockIdx.x;
    const int q0 = qt * 64, kh = h >> 2;
    const float scale = 0.08838834764831845f;   // 1/sqrt(128)

    // Q A-fragments (pre-scaled, tf32)
    unsigned qa[16][4];
    {
        const float* qr0 = q + (size_t)(q0 + w * 16 + g) * DIM + h * HD;
        const float* qr1 = qr0 + (size_t)8 * DIM;
        #pragma unroll
        for (int ks = 0; ks < 16; ks++) {
            qa[ks][0] = f2tf(qr0[ks * 8 + tg] * scale);
            qa[ks][1] = f2tf(qr1[ks * 8 + tg] * scale);
            qa[ks][2] = f2tf(qr0[ks * 8 + tg + 4] * scale);
            qa[ks][3] = f2tf(qr1[ks * 8 + tg + 4] * scale);
        }
    }

    float m0 = -1e30f, m1 = -1e30f, l0 = 0.f, l1 = 0.f;
    float oacc[16][4];
    #pragma unroll
    for (int nf = 0; nf < 16; nf++)
        #pragma unroll
        for (int c = 0; c < 4; c++) oacc[nf][c] = 0.f;

    for (int kt = 0; kt <= qt; ++kt) {
        __syncthreads();   // prev iter done with Ks/Vs
        // ---- load K,V tiles (tf32 into smem)
        const float* kb = k + (size_t)(kt * 64) * KVDIM + kh * HD;
        const float* vb = v + (size_t)(kt * 64) * KVDIM + kh * HD;
        for (int i = tid; i < 64 * 32; i += 128) {
            int r = i >> 5, c4 = (i & 31) * 4;
            float4 kv = *(const float4*)(kb + (size_t)r * KVDIM + c4);
            uint4 kk; kk.x = f2tf(kv.x); kk.y = f2tf(kv.y);
                      kk.z = f2tf(kv.z); kk.w = f2tf(kv.w);
            *(uint4*)&Ks[r * KSTR + c4] = kk;
            float4 vv = *(const float4*)(vb + (size_t)r * KVDIM + c4);
            uint4 vk; vk.x = f2tf(vv.x); vk.y = f2tf(vv.y);
                      vk.z = f2tf(vv.z); vk.w = f2tf(vv.w);
            *(uint4*)&Vs[r * VSTR + c4] = vk;
        }
        __syncthreads();

        // ---- S = Q @ K^T   (warp: 16 rows x 64 cols)
        float s[8][4];
        #pragma unroll
        for (int nf = 0; nf < 8; nf++)
            #pragma unroll
            for (int c = 0; c < 4; c++) s[nf][c] = 0.f;

        #pragma unroll
        for (int ks = 0; ks < 16; ks++) {
            #pragma unroll
            for (int nf = 0; nf < 8; nf++) {
                unsigned b0 = Ks[(nf * 8 + g) * KSTR + ks * 8 + tg];
                unsigned b1 = Ks[(nf * 8 + g) * KSTR + ks * 8 + tg + 4];
                mma8(s[nf], qa[ks][0], qa[ks][1], qa[ks][2], qa[ks][3], b0, b1);
            }
        }

        // ---- causal mask on the diagonal tile
        if (kt == qt) {
            int r0 = w * 16 + g, r1 = r0 + 8;
            #pragma unroll
            for (int nf = 0; nf < 8; nf++) {
                int c = nf * 8 + tg * 2;
                if (c     > r0) s[nf][0] = -1e30f;
                if (c + 1 > r0) s[nf][1] = -1e30f;
                if (c     > r1) s[nf][2] = -1e30f;
                if (c + 1 > r1) s[nf][3] = -1e30f;
            }
        }

        // ---- online softmax (rows g and g+8; reduce over 4-lane quad)
        float mx0 = -1e30f, mx1 = -1e30f;
        #pragma unroll
        for (int nf = 0; nf < 8; nf++) {
            mx0 = fmaxf(mx0, fmaxf(s[nf][0], s[nf][1]));
            mx1 = fmaxf(mx1, fmaxf(s[nf][2], s[nf][3]));
        }
        mx0 = fmaxf(mx0, __shfl_xor_sync(0xffffffffu, mx0, 1));
        mx0 = fmaxf(mx0, __shfl_xor_sync(0xffffffffu, mx0, 2));
        mx1 = fmaxf(mx1, __shfl_xor_sync(0xffffffffu, mx1, 1));
        mx1 = fmaxf(mx1, __shfl_xor_sync(0xffffffffu, mx1, 2));

        float mn0 = fmaxf(m0, mx0), mn1 = fmaxf(m1, mx1);
        float al0 = __expf(m0 - mn0), al1 = __expf(m1 - mn1);
        float rs0 = 0.f, rs1 = 0.f;
        const int pr0 = (w * 16 + g) * PSTR;
        const int pr1 = pr0 + 8 * PSTR;
        #pragma unroll
        for (int nf = 0; nf < 8; nf++) {
            float p0 = __expf(s[nf][0] - mn0);
            float p1 = __expf(s[nf][1] - mn0);
            float p2 = __expf(s[nf][2] - mn1);
            float p3 = __expf(s[nf][3] - mn1);
            rs0 += p0 + p1; rs1 += p2 + p3;
            uint2 w0; w0.x = f2tf(p0); w0.y = f2tf(p1);
            uint2 w1; w1.x = f2tf(p2); w1.y = f2tf(p3);
            *(uint2*)&Ps[pr0 + nf * 8 + tg * 2] = w0;
            *(uint2*)&Ps[pr1 + nf * 8 + tg * 2] = w1;
        }
        rs0 += __shfl_xor_sync(0xffffffffu, rs0, 1);
        rs0 += __shfl_xor_sync(0xffffffffu, rs0, 2);
        rs1 += __shfl_xor_sync(0xffffffffu, rs1, 1);
        rs1 += __shfl_xor_sync(0xffffffffu, rs1, 2);
        l0 = l0 * al0 + rs0;  l1 = l1 * al1 + rs1;
        m0 = mn0;  m1 = mn1;
        #pragma unroll
        for (int nf = 0; nf < 16; nf++) {
            oacc[nf][0] *= al0; oacc[nf][1] *= al0;
            oacc[nf][2] *= al1; oacc[nf][3] *= al1;
        }
        __syncwarp();   // Ps is warp-private: warp-level visibility suffices

        // ---- O += P @ V   (warp: 16 rows x 128 cols over k=64)
        #pragma unroll
        for (int ks = 0; ks < 8; ks++) {
            unsigned a0 = Ps[pr0 + ks * 8 + tg];
            unsigned a1 = Ps[pr1 + ks * 8 + tg];
            unsigned a2 = Ps[pr0 + ks * 8 + tg + 4];
            unsigned a3 = Ps[pr1 + ks * 8 + tg + 4];
            #pragma unroll
            for (int nf = 0; nf < 16; nf++) {
                unsigned b0 = Vs[(ks * 8 + tg) * VSTR + nf * 8 + g];
                unsigned b1 = Vs[(ks * 8 + tg + 4) * VSTR + nf * 8 + g];
                mma8(oacc[nf], a0, a1, a2, a3, b0, b1);
            }
        }
    }

    // ---- epilogue
    float inv0 = 1.f / l0, inv1 = 1.f / l1;
    float* o0 = o + (size_t)(q0 + w * 16 + g) * DIM + h * HD;
    float* o1 = o0 + (size_t)8 * DIM;
    #pragma unroll
    for (int nf = 0; nf < 16; nf++) {
        float2 t0; t0.x = oacc[nf][0] * inv0; t0.y = oacc[nf][1] * inv0;
        float2 t1; t1.x = oacc[nf][2] * inv1; t1.y = oacc[nf][3] * inv1;
        *(float2*)&o0[nf * 8 + tg * 2] = t0;
        *(float2*)&o1[nf * 8 + tg * 2] = t1;
    }
}

// ---------------- launch ----------------------------------------------------
extern "C" void kernel_launch(void* const* d_in, const int* in_sizes, int n_in,
                              void* d_out, int out_size)
{
    const float* x  = (const float*)d_in[0];
    // d_in[1] = cache_kv: unused (start_pos==0 => cache is pass-through)
    const float* fr = (const float*)d_in[2];
    const float* wq = (const float*)d_in[3];
    const float* wk = (const float*)d_in[4];
    const float* wv = (const float*)d_in[5];
    const float* wo = (const float*)d_in[6];
    float* out = (float*)d_out;

    float *pq, *pk, *pv, *pa;
    cudaGetSymbolAddress((void**)&pq, g_q);
    cudaGetSymbolAddress((void**)&pk, g_k);
    cudaGetSymbolAddress((void**)&pv, g_v);
    cudaGetSymbolAddress((void**)&pa, g_a);

    cudaFuncSetAttribute(flash_tf32, cudaFuncAttributeMaxDynamicSharedMemorySize,
                         FLASH_SMEM);

    dim3 blk(256);
    // QKV projections (tf32 tensor cores)
    gemm_tf32<<<dim3(DIM / 128,   SEQ / 128), blk>>>(x, wq, pq, SEQ, DIM,   DIM);
    gemm_tf32<<<dim3(KVDIM / 128, SEQ / 128), blk>>>(x, wk, pk, SEQ, KVDIM, DIM);
    gemm_tf32<<<dim3(KVDIM / 128, SEQ / 128), blk>>>(x, wv, pv, SEQ, KVDIM, DIM);
    // RoPE on q and k
    const int rope_total = SEQ * (NH + NKV) * (HD / 2);
    rope_kernel<<<(rope_total + 255) / 256, 256>>>(pq, pk, fr);
    // causal GQA flash attention (tf32 tensor cores)
    flash_tf32<<<dim3(SEQ / 64, NH), 128, FLASH_SMEM>>>(pq, pk, pv, pa);
    // output projection
    gemm_tf32<<<dim3(DIM / 128, SEQ / 128), blk>>>(pa, wo, out, SEQ, DIM, DIM);
}

// round 9
// speedup vs baseline: 7.0473x; 4.3187x over previous
#include <cuda_runtime.h>
#include <cuda_fp16.h>
#include <cstdint>

#define SEQ   2048
#define DIM   4096
#define NH    32
#define NKV   8
#define HD    128
#define KVDIM 1024   // NKV*HD

// ---------------- scratch (static device globals; no allocations) ----------
__device__ float  g_q[SEQ * DIM];        // q proj fp32
__device__ float  g_k[SEQ * KVDIM];      // k proj fp32
__device__ float  g_v[SEQ * KVDIM];      // v proj fp32
__device__ __half g_xh[SEQ * DIM];       // x fp16
__device__ __half g_qh[SEQ * DIM];       // roped+scaled q fp16
__device__ __half g_kh[SEQ * KVDIM];     // roped k fp16
__device__ __half g_vh[SEQ * KVDIM];     // v fp16
__device__ __half g_ah[SEQ * DIM];       // attention out fp16
__device__ __half g_wqh[DIM * DIM];      // wq^T [N][K] fp16
__device__ __half g_wkh[KVDIM * DIM];
__device__ __half g_wvh[KVDIM * DIM];
__device__ __half g_woh[DIM * DIM];

// ---------------- PTX helpers ----------------------------------------------
__device__ __forceinline__ uint32_t smem_u32(const void* p) {
    uint32_t a;
    asm("{ .reg .u64 t; cvta.to.shared.u64 t, %1; cvt.u32.u64 %0, t; }"
        : "=r"(a) : "l"(p));
    return a;
}
__device__ __forceinline__ void cpasync16(uint32_t dst, const void* src) {
    asm volatile("cp.async.cg.shared.global [%0], [%1], 16;" :: "r"(dst), "l"(src));
}
#define CP_COMMIT() asm volatile("cp.async.commit_group;" ::: "memory")
#define CP_WAIT(N)  asm volatile("cp.async.wait_group %0;" :: "n"(N) : "memory")

__device__ __forceinline__ void ldsm4(uint32_t* r, uint32_t a) {
    asm volatile("ldmatrix.sync.aligned.m8n8.x4.shared.b16 {%0,%1,%2,%3}, [%4];"
        : "=r"(r[0]), "=r"(r[1]), "=r"(r[2]), "=r"(r[3]) : "r"(a));
}
__device__ __forceinline__ void ldsm4t(uint32_t* r, uint32_t a) {
    asm volatile("ldmatrix.sync.aligned.m8n8.x4.trans.shared.b16 {%0,%1,%2,%3}, [%4];"
        : "=r"(r[0]), "=r"(r[1]), "=r"(r[2]), "=r"(r[3]) : "r"(a));
}
// D += A(16x16) * B(16x8), fp16 in, fp32 accum
__device__ __forceinline__ void mma16(float* c, const uint32_t* a,
                                      uint32_t b0, uint32_t b1) {
    asm volatile(
        "mma.sync.aligned.m16n8k16.row.col.f32.f16.f16.f32 "
        "{%0,%1,%2,%3}, {%4,%5,%6,%7}, {%8,%9}, {%0,%1,%2,%3};"
        : "+f"(c[0]), "+f"(c[1]), "+f"(c[2]), "+f"(c[3])
        : "r"(a[0]), "r"(a[1]), "r"(a[2]), "r"(a[3]), "r"(b0), "r"(b1));
}
__device__ __forceinline__ uint32_t f2h2(float lo, float hi) {
    uint32_t d;
    asm("cvt.rn.f16x2.f32 %0, %1, %2;" : "=r"(d) : "f"(hi), "f"(lo));
    return d;
}

// ---------------- fp16 GEMM: C[M,N] = A[M,K] @ BT[N,K]^T --------------------
// 128x128x32 tile, 256 threads (8 warps 2x4, warp tile 64x32), 4-stage
// cp.async pipeline. smem rows padded to 80B: row r start word 20r mod 32
// -> 8 consecutive rows hit disjoint 4-word groups (conflict-free ldmatrix).
#define G_STAGE  20480            // A 128*80 + B 128*80
#define G_SMEM   (4 * G_STAGE)

__device__ __forceinline__ void g_fill(uint32_t sbase, int slot,
                                       const __half* __restrict__ Ab,
                                       const __half* __restrict__ Bb,
                                       int K, int kt, int tid)
{
    const uint32_t sA = sbase + slot * G_STAGE;
    const uint32_t sB = sA + 10240;
    const __half* ag = Ab + (size_t)kt * 32;
    const __half* bg = Bb + (size_t)kt * 32;
    #pragma unroll
    for (int j = 0; j < 2; j++) {
        int idx = tid + j * 256;
        int r = idx >> 2, c = idx & 3;
        cpasync16(sA + r * 80 + c * 16, ag + (size_t)r * K + c * 8);
        cpasync16(sB + r * 80 + c * 16, bg + (size_t)r * K + c * 8);
    }
    CP_COMMIT();
}

__global__ __launch_bounds__(256, 1)
void gemm_h(const __half* __restrict__ A, const __half* __restrict__ BT,
            float* __restrict__ C, int N, int K)
{
    extern __shared__ char smem[];
    const uint32_t sbase = smem_u32(smem);
    const int tid = threadIdx.x, lane = tid & 31, wid = tid >> 5;
    const int g = lane >> 2, tg = lane & 3;
    const int wm = (wid & 1) * 64, wn = (wid >> 1) * 32;
    const int rowBase = blockIdx.y * 128, colBase = blockIdx.x * 128;

    const __half* Ab = A  + (size_t)rowBase * K;
    const __half* Bb = BT + (size_t)colBase * K;
    const int T = K / 32;

    // per-lane ldmatrix base offsets
    const uint32_t aoff = (uint32_t)((wm + (lane & 15)) * 80 + (lane >> 4) * 16);
    const uint32_t boff = (uint32_t)((wn + (lane & 7) + ((lane >> 4) << 3)) * 80
                                     + ((lane >> 3) & 1) * 16);

    float acc[4][4][4];
    #pragma unroll
    for (int mi = 0; mi < 4; mi++)
        #pragma unroll
        for (int ni = 0; ni < 4; ni++)
            #pragma unroll
            for (int c = 0; c < 4; c++) acc[mi][ni][c] = 0.f;

    #pragma unroll
    for (int s = 0; s < 3; s++) g_fill(sbase, s, Ab, Bb, K, s, tid);

    for (int t = 0; t < T; t++) {
        CP_WAIT(2);
        __syncthreads();
        const uint32_t sA = sbase + (t & 3) * G_STAGE;
        const uint32_t sB = sA + 10240;
        #pragma unroll
        for (int ks = 0; ks < 2; ks++) {
            uint32_t a[4][4], b[2][4];
            #pragma unroll
            for (int mi = 0; mi < 4; mi++)
                ldsm4(a[mi], sA + aoff + mi * 1280 + ks * 32);
            #pragma unroll
            for (int nbp = 0; nbp < 2; nbp++)
                ldsm4(b[nbp], sB + boff + nbp * 1280 + ks * 32);
            #pragma unroll
            for (int mi = 0; mi < 4; mi++) {
                mma16(acc[mi][0], a[mi], b[0][0], b[0][1]);
                mma16(acc[mi][1], a[mi], b[0][2], b[0][3]);
                mma16(acc[mi][2], a[mi], b[1][0], b[1][1]);
                mma16(acc[mi][3], a[mi], b[1][2], b[1][3]);
            }
        }
        if (t + 3 < T) g_fill(sbase, (t + 3) & 3, Ab, Bb, K, t + 3, tid);
        else           CP_COMMIT();   // keep wait_group accounting uniform
    }

    #pragma unroll
    for (int mi = 0; mi < 4; mi++) {
        #pragma unroll
        for (int ni = 0; ni < 4; ni++) {
            int r0 = rowBase + wm + mi * 16 + g;
            int cc = colBase + wn + ni * 8 + tg * 2;
            float2 t0; t0.x = acc[mi][ni][0]; t0.y = acc[mi][ni][1];
            float2 t1; t1.x = acc[mi][ni][2]; t1.y = acc[mi][ni][3];
            *(float2*)&C[(size_t)r0 * N + cc]       = t0;
            *(float2*)&C[(size_t)(r0 + 8) * N + cc] = t1;
        }
    }
}

// ---------------- pre-passes -------------------------------------------------
__global__ void conv_half4(const float* __restrict__ in, __half* __restrict__ out,
                           int n4)
{
    int i = blockIdx.x * blockDim.x + threadIdx.x;
    if (i >= n4) return;
    float4 v = ((const float4*)in)[i];
    uint2 o;
    o.x = f2h2(v.x, v.y);
    o.y = f2h2(v.z, v.w);
    ((uint2*)out)[i] = o;
}

// W[K][N] fp32 row-major -> WT[N][K] fp16 row-major
__global__ void transpose_h(const float* __restrict__ W, __half* __restrict__ WT,
                            int K, int N)
{
    __shared__ float t[32][33];
    int x = blockIdx.x * 32 + threadIdx.x;
    int y0 = blockIdx.y * 32;
    #pragma unroll
    for (int j = threadIdx.y; j < 32; j += 8)
        t[j][threadIdx.x] = W[(size_t)(y0 + j) * N + x];
    __syncthreads();
    int k = y0 + threadIdx.x;
    int n0 = blockIdx.x * 32;
    #pragma unroll
    for (int j = threadIdx.y; j < 32; j += 8)
        WT[(size_t)(n0 + j) * K + k] = __float2half_rn(t[threadIdx.x][j]);
}

// ---------------- RoPE + fp16 conversion ------------------------------------
// reads fp32 q/k projections, applies rope, writes fp16 (q pre-scaled)
__global__ void rope_h(const float* __restrict__ q, const float* __restrict__ k,
                       const float* __restrict__ f,
                       __half* __restrict__ qh, __half* __restrict__ kh)
{
    int idx = blockIdx.x * blockDim.x + threadIdx.x;
    const int total = SEQ * (NH + NKV) * (HD / 2);
    if (idx >= total) return;
    int i = idx & 63;
    int h = (idx >> 6) % (NH + NKV);
    int s = idx / ((NH + NKV) * 64);
    const float scale = 0.08838834764831845f;   // 1/sqrt(128)

    float c = f[s * 128 + 2 * i];
    float d = f[s * 128 + 2 * i + 1];
    if (h < NH) {
        size_t off = (size_t)s * DIM + h * HD + 2 * i;
        float a = q[off], b = q[off + 1];
        qh[off]     = __float2half_rn((a * c - b * d) * scale);
        qh[off + 1] = __float2half_rn((a * d + b * c) * scale);
    } else {
        size_t off = (size_t)s * KVDIM + (h - NH) * HD + 2 * i;
        float a = k[off], b = k[off + 1];
        kh[off]     = __float2half_rn(a * c - b * d);
        kh[off + 1] = __float2half_rn(a * d + b * c);
    }
}

// ---------------- causal flash attention (fp16 mma, GQA) --------------------
// 128 threads = 4 warps; warp w owns q rows [w*16, w*16+16). Q in registers,
// P repacked from S accumulators (no smem). K/V tiles double-buffered cp.async.
// smem rows padded to 272B (68 words): 8 consecutive rows -> disjoint banks.
#define FKR   136                         // halves per K/V smem row
#define FTILE (64 * FKR * 2)              // 17408 B
#define F_SMEM (4 * FTILE)                // K0,V0,K1,V1

__device__ __forceinline__ void f_fill(uint32_t sbase, int buf, int kt,
                                       const __half* __restrict__ kb,
                                       const __half* __restrict__ vb, int tid)
{
    const uint32_t kd = sbase + buf * (2 * FTILE);
    const uint32_t vd = kd + FTILE;
    const __half* kg = kb + (size_t)(kt * 64) * KVDIM;
    const __half* vg = vb + (size_t)(kt * 64) * KVDIM;
    #pragma unroll
    for (int j = 0; j < 8; j++) {
        int idx = tid + j * 128;
        int r = idx >> 4, c = idx & 15;
        cpasync16(kd + r * 272 + c * 16, kg + (size_t)r * KVDIM + c * 8);
        cpasync16(vd + r * 272 + c * 16, vg + (size_t)r * KVDIM + c * 8);
    }
    CP_COMMIT();
}

__global__ __launch_bounds__(128, 2)
void flash_h(const __half* __restrict__ q, const __half* __restrict__ k,
             const __half* __restrict__ v, __half* __restrict__ o)
{
    extern __shared__ char smem[];
    const uint32_t sbase = smem_u32(smem);
    const int tid = threadIdx.x, lane = tid & 31, w = tid >> 5;
    const int g = lane >> 2, tg = lane & 3;
    const int h = blockIdx.y, qt = blockIdx.x;
    const int q0 = qt * 64, khd = h >> 2;

    const __half* kb = k + khd * HD;
    const __half* vb = v + khd * HD;

    // ---- stage Q tile into buf0-K region, ldmatrix into registers
    {
        const __half* qg = q + (size_t)q0 * DIM + h * HD;
        #pragma unroll
        for (int j = 0; j < 8; j++) {
            int idx = tid + j * 128;
            int r = idx >> 4, c = idx & 15;
            cpasync16(sbase + r * 272 + c * 16, qg + (size_t)r * DIM + c * 8);
        }
        CP_COMMIT();
        CP_WAIT(0);
        __syncthreads();
    }
    uint32_t qa[8][4];
    {
        const uint32_t qoff = sbase + (uint32_t)((w * 16 + (lane & 15)) * 272
                                                 + (lane >> 4) * 16);
        #pragma unroll
        for (int ks = 0; ks < 8; ks++) ldsm4(qa[ks], qoff + ks * 32);
    }
    __syncthreads();

    float m0 = -1e30f, m1 = -1e30f, l0 = 0.f, l1 = 0.f;
    float oacc[16][4];
    #pragma unroll
    for (int nf = 0; nf < 16; nf++)
        #pragma unroll
        for (int c = 0; c < 4; c++) oacc[nf][c] = 0.f;

    // per-lane smem offsets for K (B frag) and V (trans B frag)
    const uint32_t kboff = (uint32_t)(((lane & 7) + ((lane >> 4) << 3)) * 272
                                      + ((lane >> 3) & 1) * 16);
    const uint32_t vboff = (uint32_t)(((lane & 7) + ((lane >> 3) & 1) * 8) * 272
                                      + (lane >> 4) * 16);

    f_fill(sbase, 0, 0, kb, vb, tid);

    for (int kt = 0; kt <= qt; kt++) {
        if (kt < qt) {
            f_fill(sbase, (kt + 1) & 1, kt + 1, kb, vb, tid);
            CP_WAIT(1);
        } else {
            CP_WAIT(0);
        }
        __syncthreads();
        const uint32_t kbase = sbase + (kt & 1) * (2 * FTILE);
        const uint32_t vbase = kbase + FTILE;

        // ---- S = Q @ K^T
        float s[8][4];
        #pragma unroll
        for (int nf = 0; nf < 8; nf++)
            #pragma unroll
            for (int c = 0; c < 4; c++) s[nf][c] = 0.f;
        #pragma unroll
        for (int ks = 0; ks < 8; ks++) {
            #pragma unroll
            for (int nbp = 0; nbp < 4; nbp++) {
                uint32_t b[4];
                ldsm4(b, kbase + kboff + nbp * 16 * 272 + ks * 32);
                mma16(s[nbp * 2],     qa[ks], b[0], b[1]);
                mma16(s[nbp * 2 + 1], qa[ks], b[2], b[3]);
            }
        }

        // ---- causal mask on diagonal tile
        if (kt == qt) {
            int r0 = w * 16 + g, r1 = r0 + 8;
            #pragma unroll
            for (int nf = 0; nf < 8; nf++) {
                int c = nf * 8 + tg * 2;
                if (c     > r0) s[nf][0] = -1e30f;
                if (c + 1 > r0) s[nf][1] = -1e30f;
                if (c     > r1) s[nf][2] = -1e30f;
                if (c + 1 > r1) s[nf][3] = -1e30f;
            }
        }

        // ---- online softmax; P packed to fp16 registers
        float mx0 = -1e30f, mx1 = -1e30f;
        #pragma unroll
        for (int nf = 0; nf < 8; nf++) {
            mx0 = fmaxf(mx0, fmaxf(s[nf][0], s[nf][1]));
            mx1 = fmaxf(mx1, fmaxf(s[nf][2], s[nf][3]));
        }
        mx0 = fmaxf(mx0, __shfl_xor_sync(0xffffffffu, mx0, 1));
        mx0 = fmaxf(mx0, __shfl_xor_sync(0xffffffffu, mx0, 2));
        mx1 = fmaxf(mx1, __shfl_xor_sync(0xffffffffu, mx1, 1));
        mx1 = fmaxf(mx1, __shfl_xor_sync(0xffffffffu, mx1, 2));

        float mn0 = fmaxf(m0, mx0), mn1 = fmaxf(m1, mx1);
        float al0 = __expf(m0 - mn0), al1 = __expf(m1 - mn1);
        float rs0 = 0.f, rs1 = 0.f;
        uint32_t ph[8][2];
        #pragma unroll
        for (int nf = 0; nf < 8; nf++) {
            float p0 = __expf(s[nf][0] - mn0);
            float p1 = __expf(s[nf][1] - mn0);
            float p2 = __expf(s[nf][2] - mn1);
            float p3 = __expf(s[nf][3] - mn1);
            rs0 += p0 + p1; rs1 += p2 + p3;
            ph[nf][0] = f2h2(p0, p1);   // row g
            ph[nf][1] = f2h2(p2, p3);   // row g+8
        }
        rs0 += __shfl_xor_sync(0xffffffffu, rs0, 1);
        rs0 += __shfl_xor_sync(0xffffffffu, rs0, 2);
        rs1 += __shfl_xor_sync(0xffffffffu, rs1, 1);
        rs1 += __shfl_xor_sync(0xffffffffu, rs1, 2);
        l0 = l0 * al0 + rs0;  l1 = l1 * al1 + rs1;
        m0 = mn0;  m1 = mn1;
        #pragma unroll
        for (int nf = 0; nf < 16; nf++) {
            oacc[nf][0] *= al0; oacc[nf][1] *= al0;
            oacc[nf][2] *= al1; oacc[nf][3] *= al1;
        }

        // ---- O += P @ V   (V via ldmatrix.trans)
        #pragma unroll
        for (int ksv = 0; ksv < 4; ksv++) {
            uint32_t a[4];
            a[0] = ph[2 * ksv][0];     a[1] = ph[2 * ksv][1];
            a[2] = ph[2 * ksv + 1][0]; a[3] = ph[2 * ksv + 1][1];
            #pragma unroll
            for (int nbp = 0; nbp < 8; nbp++) {
                uint32_t b[4];
                ldsm4t(b, vbase + vboff + ksv * 16 * 272 + nbp * 32);
                mma16(oacc[nbp * 2],     a, b[0], b[1]);
                mma16(oacc[nbp * 2 + 1], a, b[2], b[3]);
            }
        }
        __syncthreads();   // all warps done with this buffer before refill
    }

    // ---- epilogue: fp16 store (A operand of the wo GEMM)
    float inv0 = 1.f / l0, inv1 = 1.f / l1;
    __half* o0 = o + (size_t)(q0 + w * 16 + g) * DIM + h * HD;
    __half* o1 = o0 + (size_t)8 * DIM;
    #pragma unroll
    for (int nf = 0; nf < 16; nf++) {
        *(uint32_t*)&o0[nf * 8 + tg * 2] = f2h2(oacc[nf][0] * inv0, oacc[nf][1] * inv0);
        *(uint32_t*)&o1[nf * 8 + tg * 2] = f2h2(oacc[nf][2] * inv1, oacc[nf][3] * inv1);
    }
}

// ---------------- launch ------------------------------------------------------
extern "C" void kernel_launch(void* const* d_in, const int* in_sizes, int n_in,
                              void* d_out, int out_size)
{
    const float* x  = (const float*)d_in[0];
    // d_in[1] = cache_kv: unused (start_pos==0 => cache is pass-through)
    const float* fr = (const float*)d_in[2];
    const float* wq = (const float*)d_in[3];
    const float* wk = (const float*)d_in[4];
    const float* wv = (const float*)d_in[5];
    const float* wo = (const float*)d_in[6];
    float* out = (float*)d_out;

    float  *pq, *pk, *pv;
    __half *pxh, *pqh, *pkh, *pvh, *pah, *pwq, *pwk, *pwv, *pwo;
    cudaGetSymbolAddress((void**)&pq,  g_q);
    cudaGetSymbolAddress((void**)&pk,  g_k);
    cudaGetSymbolAddress((void**)&pv,  g_v);
    cudaGetSymbolAddress((void**)&pxh, g_xh);
    cudaGetSymbolAddress((void**)&pqh, g_qh);
    cudaGetSymbolAddress((void**)&pkh, g_kh);
    cudaGetSymbolAddress((void**)&pvh, g_vh);
    cudaGetSymbolAddress((void**)&pah, g_ah);
    cudaGetSymbolAddress((void**)&pwq, g_wqh);
    cudaGetSymbolAddress((void**)&pwk, g_wkh);
    cudaGetSymbolAddress((void**)&pwv, g_wvh);
    cudaGetSymbolAddress((void**)&pwo, g_woh);

    cudaFuncSetAttribute(gemm_h, cudaFuncAttributeMaxDynamicSharedMemorySize, G_SMEM);
    cudaFuncSetAttribute(flash_h, cudaFuncAttributeMaxDynamicSharedMemorySize, F_SMEM);

    // --- pre-passes: fp16 conversion (+ weight transpose to [N][K]) ---
    conv_half4<<<(SEQ * DIM / 4 + 255) / 256, 256>>>(x, pxh, SEQ * DIM / 4);
    dim3 tb(32, 8);
    transpose_h<<<dim3(DIM / 32,   DIM / 32), tb>>>(wq, pwq, DIM, DIM);
    transpose_h<<<dim3(KVDIM / 32, DIM / 32), tb>>>(wk, pwk, DIM, KVDIM);
    transpose_h<<<dim3(KVDIM / 32, DIM / 32), tb>>>(wv, pwv, DIM, KVDIM);
    transpose_h<<<dim3(DIM / 32,   DIM / 32), tb>>>(wo, pwo, DIM, DIM);

    // --- QKV projections (fp16 mma, fp32 accum/out) ---
    gemm_h<<<dim3(DIM / 128,   SEQ / 128), 256, G_SMEM>>>(pxh, pwq, pq, DIM,   DIM);
    gemm_h<<<dim3(KVDIM / 128, SEQ / 128), 256, G_SMEM>>>(pxh, pwk, pk, KVDIM, DIM);
    gemm_h<<<dim3(KVDIM / 128, SEQ / 128), 256, G_SMEM>>>(pxh, pwv, pv, KVDIM, DIM);

    // --- RoPE + fp16 conversion, V conversion ---
    const int rope_total = SEQ * (NH + NKV) * (HD / 2);
    rope_h<<<(rope_total + 255) / 256, 256>>>(pq, pk, fr, pqh, pkh);
    conv_half4<<<(SEQ * KVDIM / 4 + 255) / 256, 256>>>(pv, pvh, SEQ * KVDIM / 4);

    // --- causal GQA flash attention (fp16 mma) ---
    flash_h<<<dim3(SEQ / 64, NH), 128, F_SMEM>>>(pqh, pkh, pvh, pah);

    // --- output projection ---
    gemm_h<<<dim3(DIM / 128, SEQ / 128), 256, G_SMEM>>>(pah, pwo, out, DIM, DIM);
}